// round 5
// baseline (speedup 1.0000x reference)
#include <cuda_runtime.h>
#include <math.h>

#define Bq 16
#define Sq 2048
#define Hq 512
#define Oq 16
#define BSq (Bq*Sq)            // 32768
#define RSQRT_H 0.04419417382415922f   // 1/sqrt(512)

typedef unsigned long long ull;

__device__ __forceinline__ ull ffma2(ull a, ull b, ull c) {
    ull d; asm("fma.rn.f32x2 %0, %1, %2, %3;" : "=l"(d) : "l"(a), "l"(b), "l"(c));
    return d;
}
__device__ __forceinline__ ull addf2(ull a, ull b) {
    ull d; asm("add.rn.f32x2 %0, %1, %2;" : "=l"(d) : "l"(a), "l"(b));
    return d;
}
__device__ __forceinline__ ull dup2(float f) {
    ull r; asm("mov.b64 %0, {%1, %1};" : "=l"(r) : "f"(f));
    return r;
}

// ---------------- scratch (device globals) ----------------------------------
__device__ float g_oq[Oq*Hq];              // raw operator queries (atomic accum)
__device__ float g_kq[Oq*Hq];              // oq @ Wk, pre-scaled  [o][k]
__device__ float g_c[Oq];                  // bk . oq, pre-scaled
__device__ float g_logits[BSq*Oq];         // [b][s][o]
__device__ float g_esum[Bq*Oq];            // sum_s exp(logits)  (atomic)
__device__ float g_W[Bq*Oq];               // sum_s w (UNnormalized, atomic)
__device__ float g_up[64*Bq*Oq*Hq];        // split-s partials of u (unnormalized)
__device__ float g_u[Bq*Oq*Hq];            // sum_s w * x (unnormalized)
__device__ float g_opout[Bq*Oq*Hq];        // operator outputs

// ---------------- K-zero -----------------------------------------------------
__global__ void kzero() {
    int i = blockIdx.x * 256 + threadIdx.x;
    if (i < Oq*Hq) g_oq[i] = 0.f;
    if (i < Bq*Oq) { g_esum[i] = 0.f; g_W[i] = 0.f; }
}

// ---------------- K0a: oq[o][h] = sum_s ops[s][o] * Wq_op[h][s] --------------
__global__ void __launch_bounds__(512) k0a(const float* __restrict__ Wq_op,
                                           const float* __restrict__ ops) {
    __shared__ float ops_sh[128*16];
    __shared__ float wq_sh[64][129];
    int h0 = blockIdx.x * 64, s0 = blockIdx.y * 128;
    for (int i = threadIdx.x; i < 128*16; i += 512)
        ops_sh[i] = ops[s0*16 + i];
    for (int i = threadIdx.x; i < 64*128; i += 512) {
        int r = i >> 7, c = i & 127;
        wq_sh[r][c] = Wq_op[(size_t)(h0 + r)*Sq + s0 + c];
    }
    __syncthreads();
    int hl = threadIdx.x & 63;
    int og = threadIdx.x >> 6;
    float a0 = 0.f, a1 = 0.f;
    #pragma unroll 8
    for (int s = 0; s < 128; s++) {
        float wv = wq_sh[hl][s];
        a0 += wv * ops_sh[s*16 + og*2];
        a1 += wv * ops_sh[s*16 + og*2 + 1];
    }
    atomicAdd(&g_oq[(og*2    )*Hq + h0 + hl], a0);
    atomicAdd(&g_oq[(og*2 + 1)*Hq + h0 + hl], a1);
}

// ---------------- K0b: kq[o][k] = (oq+bq)@Wk * rs; c = bk.(oq+bq)*rs ---------
__global__ void __launch_bounds__(128) k0b(const float* __restrict__ Wk,
                                           const float* __restrict__ bk,
                                           const float* __restrict__ bq,
                                           float* oq_out) {
    __shared__ float oq_sh[Hq];
    __shared__ float red[4][33];
    __shared__ float cr[128];
    int o = blockIdx.x, kc = blockIdx.y;
    for (int h = threadIdx.x; h < Hq; h += 128) {
        float v = g_oq[o*Hq + h] + bq[h];
        oq_sh[h] = v;
        if (kc == 0 && oq_out) oq_out[o*Hq + h] = v;
    }
    __syncthreads();
    int kl = threadIdx.x & 31, hq = threadIdx.x >> 5;
    int k = kc*32 + kl;
    const float* wp = Wk + (size_t)(hq*128)*Hq + k;
    float a = 0.f;
    #pragma unroll 16
    for (int h = 0; h < 128; h++)
        a += oq_sh[hq*128 + h] * wp[(size_t)h*Hq];
    red[hq][kl] = a;
    __syncthreads();
    if (hq == 0)
        g_kq[o*Hq + k] = (red[0][kl] + red[1][kl] + red[2][kl] + red[3][kl]) * RSQRT_H;
    if (kc == 0) {
        float cl = 0.f;
        for (int h = threadIdx.x; h < Hq; h += 128) cl += bk[h] * oq_sh[h];
        cr[threadIdx.x] = cl;
        __syncthreads();
        for (int st = 64; st > 0; st >>= 1) {
            if (threadIdx.x < st) cr[threadIdx.x] += cr[threadIdx.x + st];
            __syncthreads();
        }
        if (threadIdx.x == 0) g_c[o] = cr[0] * RSQRT_H;
    }
}

// fold-reduce 8 ull (f32x2 pairs) over 32 lanes; after: lane l (even, <16)
// holds pair index p = (l>>1)&7 in v[0]
__device__ __forceinline__ void fold8(ull v[8], int lane) {
    #pragma unroll
    for (int i = 0; i < 8; i++)
        v[i] = addf2(v[i], __shfl_xor_sync(0xffffffffu, v[i], 16));
    #pragma unroll
    for (int i = 0; i < 4; i++) {
        ull mn = (lane & 8) ? v[i+4] : v[i];
        ull th = (lane & 8) ? v[i] : v[i+4];
        v[i] = addf2(mn, __shfl_xor_sync(0xffffffffu, th, 8));
    }
    #pragma unroll
    for (int i = 0; i < 2; i++) {
        ull mn = (lane & 4) ? v[i+2] : v[i];
        ull th = (lane & 4) ? v[i] : v[i+2];
        v[i] = addf2(mn, __shfl_xor_sync(0xffffffffu, th, 4));
    }
    {
        ull mn = (lane & 2) ? v[1] : v[0];
        ull th = (lane & 2) ? v[0] : v[1];
        v[0] = addf2(mn, __shfl_xor_sync(0xffffffffu, th, 2));
    }
    v[0] = addf2(v[0], __shfl_xor_sync(0xffffffffu, v[0], 1));
}

// ---------------- kB: fused logits + esum/W + unnormalized u partial ---------
// grid (64 sc, 16 b), 512 threads; 32 rows per block.
// Phase1: 16 warps = 8 row-groups x 2 o-halves; FFMA2 packed over k-pairs.
// Phase2: thread = one k column, accumulate over the 32 tile rows (x L1-hot).
__global__ void __launch_bounds__(512) kB(const float* __restrict__ x,
                                          const float* __restrict__ ops) {
    __shared__ __align__(16) float kq_sh[Oq*Hq];   // 32KB [o][k]
    __shared__ float c_sh[16];
    __shared__ float st[32*16];
    __shared__ __align__(16) float w_sh[32*16];
    __shared__ float esr[32][17];
    __shared__ float wsr[32][17];
    int tid = threadIdx.x;
    int sc = blockIdx.x, b = blockIdx.y;
    int s0 = sc * 32;
    size_t grow0 = (size_t)b * Sq + s0;

    for (int i = tid; i < Oq*Hq/4; i += 512)
        ((float4*)kq_sh)[i] = ((const float4*)g_kq)[i];
    if (tid < 16) c_sh[tid] = g_c[tid];
    __syncthreads();

    int wid = tid >> 5, lane = tid & 31;
    int rg = wid >> 1, oh = wid & 1;

    // ---- phase 1: logits (o-split, k-pair FFMA2) ----
    {
        const ulonglong2* xr = ((const ulonglong2*)x) + (grow0 + rg*4) * 128;
        const ulonglong2* kq2 = (const ulonglong2*)kq_sh;
        ull acc[4][8];
        #pragma unroll
        for (int r = 0; r < 4; r++)
            #pragma unroll
            for (int o = 0; o < 8; o++) acc[r][o] = 0ull;
        #pragma unroll
        for (int jj = 0; jj < 4; jj++) {
            int j = jj*32 + lane;
            ulonglong2 x0 = xr[j], x1 = xr[128+j], x2 = xr[256+j], x3 = xr[384+j];
            #pragma unroll
            for (int o = 0; o < 8; o++) {
                ulonglong2 kv = kq2[(oh*8 + o)*128 + j];
                acc[0][o] = ffma2(x0.x, kv.x, acc[0][o]);
                acc[0][o] = ffma2(x0.y, kv.y, acc[0][o]);
                acc[1][o] = ffma2(x1.x, kv.x, acc[1][o]);
                acc[1][o] = ffma2(x1.y, kv.y, acc[1][o]);
                acc[2][o] = ffma2(x2.x, kv.x, acc[2][o]);
                acc[2][o] = ffma2(x2.y, kv.y, acc[2][o]);
                acc[3][o] = ffma2(x3.x, kv.x, acc[3][o]);
                acc[3][o] = ffma2(x3.y, kv.y, acc[3][o]);
            }
        }
        #pragma unroll
        for (int r = 0; r < 4; r++) {
            fold8(acc[r], lane);
            if (lane < 16 && !(lane & 1)) {
                float lo, hi;
                asm("mov.b64 {%0,%1}, %2;" : "=f"(lo), "=f"(hi) : "l"(acc[r][0]));
                st[(rg*4 + r)*16 + oh*8 + ((lane >> 1) & 7)] = lo + hi;
            }
        }
    }
    __syncthreads();

    // ---- step B: +c, store logits, build unnormalized w, partial sums ----
    {
        int o = tid & 15, lr = tid >> 4;
        float v = st[tid] + c_sh[o];
        g_logits[grow0*16 + tid] = v;          // tid == lr*16+o, coalesced
        float e = __expf(v);
        float w = e * ops[s0*16 + tid];
        w_sh[tid] = w;
        esr[lr][o] = e;
        wsr[lr][o] = w;
    }
    __syncthreads();
    if (tid < 16) {
        float se = 0.f, sw = 0.f;
        #pragma unroll
        for (int j = 0; j < 32; j++) { se += esr[j][tid]; sw += wsr[j][tid]; }
        atomicAdd(&g_esum[b*16 + tid], se);
        atomicAdd(&g_W[b*16 + tid], sw);
    }

    // ---- phase 2: u partial = sum_{s in tile} w[s,o] * x[s,k] (x L1-hot) ----
    {
        const float* xq = x + grow0*512 + tid;
        ull a2[8];
        #pragma unroll
        for (int p = 0; p < 8; p++) a2[p] = 0ull;
        #pragma unroll 8
        for (int s = 0; s < 32; s++) {
            ull xa = dup2(xq[(size_t)s*512]);
            const ulonglong2* w2 = (const ulonglong2*)(w_sh + s*16);
            ulonglong2 wa = w2[0], wb = w2[1], wc = w2[2], wd = w2[3];
            a2[0] = ffma2(xa, wa.x, a2[0]); a2[1] = ffma2(xa, wa.y, a2[1]);
            a2[2] = ffma2(xa, wb.x, a2[2]); a2[3] = ffma2(xa, wb.y, a2[3]);
            a2[4] = ffma2(xa, wc.x, a2[4]); a2[5] = ffma2(xa, wc.y, a2[5]);
            a2[6] = ffma2(xa, wd.x, a2[6]); a2[7] = ffma2(xa, wd.y, a2[7]);
        }
        float* up = g_up + (size_t)(sc*16 + b) * 8192;
        #pragma unroll
        for (int p = 0; p < 8; p++) {
            float lo, hi;
            asm("mov.b64 {%0,%1}, %2;" : "=f"(lo), "=f"(hi) : "l"(a2[p]));
            up[(2*p)*512   + tid] = lo;
            up[(2*p+1)*512 + tid] = hi;
        }
    }
}

// ---------------- Ksum: u = sum of 64 split-s partials -----------------------
__global__ void ksum() {
    int i = blockIdx.x*256 + threadIdx.x;   // 32768 float4s
    int b = i >> 11, w4 = i & 2047;
    const float4* up4 = (const float4*)g_up;
    float4 s = make_float4(0.f, 0.f, 0.f, 0.f);
    #pragma unroll 8
    for (int p = 0; p < 64; p++) {
        float4 t = up4[(size_t)(p*16 + b)*2048 + w4];
        s.x += t.x; s.y += t.y; s.z += t.z; s.w += t.w;
    }
    ((float4*)g_u)[i] = s;
}

// fold-reduce 16 floats over 32 lanes; lane l (<16) ends holding total of v[l]
__device__ __forceinline__ float fold16(float v[16], int lane) {
    #pragma unroll
    for (int i = 0; i < 16; i++)
        v[i] += __shfl_xor_sync(0xffffffffu, v[i], 16);
    #pragma unroll
    for (int i = 0; i < 8; i++) {
        float mn = (lane & 8) ? v[i+8] : v[i];
        float th = (lane & 8) ? v[i] : v[i+8];
        v[i] = mn + __shfl_xor_sync(0xffffffffu, th, 8);
    }
    #pragma unroll
    for (int i = 0; i < 4; i++) {
        float mn = (lane & 4) ? v[i+4] : v[i];
        float th = (lane & 4) ? v[i] : v[i+4];
        v[i] = mn + __shfl_xor_sync(0xffffffffu, th, 4);
    }
    #pragma unroll
    for (int i = 0; i < 2; i++) {
        float mn = (lane & 2) ? v[i+2] : v[i];
        float th = (lane & 2) ? v[i] : v[i+2];
        v[i] = mn + __shfl_xor_sync(0xffffffffu, th, 2);
    }
    {
        float mn = (lane & 1) ? v[1] : v[0];
        float th = (lane & 1) ? v[0] : v[1];
        v[0] = mn + __shfl_xor_sync(0xffffffffu, th, 1);
    }
    return v[0];
}

// ---------------- K3: op_out = (u @ Wv^T)*inv + bv*(W*inv) -------------------
// grid (16 o, 8 hc of 64), 256 threads
__global__ void __launch_bounds__(256) k3(const float* __restrict__ Wv,
                                          const float* __restrict__ bv) {
    __shared__ float4 u4[16*128];
    __shared__ float inv_sh[16], Wn_sh[16];
    int o = blockIdx.x, hc = blockIdx.y;
    for (int i = threadIdx.x; i < 16*128; i += 256) {
        int b = i >> 7, k4 = i & 127;
        u4[i] = ((const float4*)g_u)[((size_t)b*16 + o)*128 + k4];
    }
    if (threadIdx.x < 16) {
        float iv = 1.0f / g_esum[threadIdx.x*16 + o];
        inv_sh[threadIdx.x] = iv;
        Wn_sh[threadIdx.x]  = g_W[threadIdx.x*16 + o] * iv;
    }
    __syncthreads();
    int wid = threadIdx.x >> 5, lane = threadIdx.x & 31;
    for (int q = 0; q < 2; q++) {
        int h = hc*64 + wid*8 + q*4;
        const float4* wv = ((const float4*)Wv) + (size_t)h * 128;
        float acc[4][16];
        #pragma unroll
        for (int r = 0; r < 4; r++)
            #pragma unroll
            for (int b = 0; b < 16; b++) acc[r][b] = 0.f;
        #pragma unroll
        for (int jj = 0; jj < 4; jj++) {
            int j = jj*32 + lane;
            float4 v0 = wv[j], v1 = wv[128+j], v2 = wv[256+j], v3 = wv[384+j];
            #pragma unroll
            for (int b = 0; b < 16; b++) {
                float4 uu = u4[b*128 + j];
                acc[0][b] += v0.x*uu.x + v0.y*uu.y + v0.z*uu.z + v0.w*uu.w;
                acc[1][b] += v1.x*uu.x + v1.y*uu.y + v1.z*uu.z + v1.w*uu.w;
                acc[2][b] += v2.x*uu.x + v2.y*uu.y + v2.z*uu.z + v2.w*uu.w;
                acc[3][b] += v3.x*uu.x + v3.y*uu.y + v3.z*uu.z + v3.w*uu.w;
            }
        }
        #pragma unroll
        for (int r = 0; r < 4; r++) {
            float t = fold16(acc[r], lane);
            if (lane < 16)
                g_opout[((size_t)lane*16 + o)*Hq + h + r] =
                    t * inv_sh[lane] + bv[h + r] * Wn_sh[lane];
        }
    }
}

// ---------------- K4: out[b,s,h] = sum_o softmax_o(L)[o]*op_out[b,o,h] ------
__global__ void __launch_bounds__(256) k4(float* __restrict__ out) {
    __shared__ __align__(16) float4 op4[16*128];
    int b = blockIdx.y, sc = blockIdx.x;
    for (int i = threadIdx.x; i < 16*128; i += 256)
        op4[i] = ((const float4*)g_opout)[(size_t)b*2048 + i];
    __syncthreads();
    int wid = threadIdx.x >> 5, lane = threadIdx.x & 31;
    for (int q = 0; q < 2; q++) {
        int s0 = sc*64 + wid*8 + q*4;
        size_t r0 = (size_t)b*Sq + s0;
        const float* lp = g_logits + (r0 + (lane & 3)) * 16;
        float e[16];
        float mx = -1e30f;
        #pragma unroll
        for (int o = 0; o < 16; o++) { e[o] = lp[o]; mx = fmaxf(mx, e[o]); }
        float sum = 0.f;
        #pragma unroll
        for (int o = 0; o < 16; o++) { e[o] = __expf(e[o] - mx); sum += e[o]; }
        float inv = 1.0f / sum;
        float ow0[16], ow1[16], ow2[16], ow3[16];
        #pragma unroll
        for (int o = 0; o < 16; o++) {
            float v = e[o] * inv;
            ow0[o] = __shfl_sync(0xffffffffu, v, 0, 4);
            ow1[o] = __shfl_sync(0xffffffffu, v, 1, 4);
            ow2[o] = __shfl_sync(0xffffffffu, v, 2, 4);
            ow3[o] = __shfl_sync(0xffffffffu, v, 3, 4);
        }
        ulonglong2* o2 = (ulonglong2*)(((float4*)out) + r0 * 128);
        #pragma unroll
        for (int jj = 0; jj < 4; jj++) {
            int j = jj*32 + lane;
            ull A0[2] = {0ull,0ull}, A1[2] = {0ull,0ull};
            ull A2[2] = {0ull,0ull}, A3[2] = {0ull,0ull};
            #pragma unroll
            for (int o = 0; o < 16; o++) {
                ulonglong2 kk = ((const ulonglong2*)op4)[o*128 + j];
                ull d0 = dup2(ow0[o]), d1 = dup2(ow1[o]);
                ull d2 = dup2(ow2[o]), d3 = dup2(ow3[o]);
                A0[0] = ffma2(d0, kk.x, A0[0]); A0[1] = ffma2(d0, kk.y, A0[1]);
                A1[0] = ffma2(d1, kk.x, A1[0]); A1[1] = ffma2(d1, kk.y, A1[1]);
                A2[0] = ffma2(d2, kk.x, A2[0]); A2[1] = ffma2(d2, kk.y, A2[1]);
                A3[0] = ffma2(d3, kk.x, A3[0]); A3[1] = ffma2(d3, kk.y, A3[1]);
            }
            o2[j]        = make_ulonglong2(A0[0], A0[1]);
            o2[128 + j]  = make_ulonglong2(A1[0], A1[1]);
            o2[256 + j]  = make_ulonglong2(A2[0], A2[1]);
            o2[384 + j]  = make_ulonglong2(A3[0], A3[1]);
        }
    }
}

// ---------------------------------------------------------------------------
extern "C" void kernel_launch(void* const* d_in, const int* in_sizes, int n_in,
                              void* d_out, int out_size) {
    const float* x     = (const float*)d_in[0];
    const float* Wv    = (const float*)d_in[1];
    const float* bv    = (const float*)d_in[2];
    const float* Wk    = (const float*)d_in[3];
    const float* bk    = (const float*)d_in[4];
    const float* Wq_op = (const float*)d_in[5];
    const float* bq_op = (const float*)d_in[6];
    const float* ops   = (const float*)d_in[7];
    (void)in_sizes; (void)n_in;
    float* out = (float*)d_out;
    float* oq_out = (out_size >= Bq*Sq*Hq + Oq*Hq) ? out + (size_t)Bq*Sq*Hq : nullptr;

    kzero<<<32, 256>>>();
    k0a<<<dim3(8, 16), 512>>>(Wq_op, ops);
    k0b<<<dim3(16, 16), 128>>>(Wk, bk, bq_op, oq_out);
    kB<<<dim3(64, 16), 512>>>(x, ops);
    ksum<<<128, 256>>>();
    k3<<<dim3(16, 8), 256>>>(Wv, bv);
    k4<<<dim3(32, 16), 256>>>(out);
}

// round 6
// speedup vs baseline: 1.0278x; 1.0278x over previous
#include <cuda_runtime.h>
#include <math.h>

#define Bq 16
#define Sq 2048
#define Hq 512
#define Oq 16
#define BSq (Bq*Sq)            // 32768
#define RSQRT_H 0.04419417382415922f   // 1/sqrt(512)

typedef unsigned long long ull;

__device__ __forceinline__ ull ffma2(ull a, ull b, ull c) {
    ull d; asm("fma.rn.f32x2 %0, %1, %2, %3;" : "=l"(d) : "l"(a), "l"(b), "l"(c));
    return d;
}
__device__ __forceinline__ ull addf2(ull a, ull b) {
    ull d; asm("add.rn.f32x2 %0, %1, %2;" : "=l"(d) : "l"(a), "l"(b));
    return d;
}
__device__ __forceinline__ ull dup2(float f) {
    ull r; asm("mov.b64 %0, {%1, %1};" : "=l"(r) : "f"(f));
    return r;
}

// ---------------- scratch (device globals) ----------------------------------
__device__ float g_oq[Oq*Hq];              // raw operator queries (atomic accum)
__device__ float g_kq[Oq*Hq];              // oq @ Wk, pre-scaled  [o][k]
__device__ float g_c[Oq];                  // bk . oq, pre-scaled
__device__ float g_logits[BSq*Oq];         // [b][s][o]
__device__ float g_esum[Bq*Oq];            // sum_s exp(logits)  (atomic)
__device__ float g_W[Bq*Oq];               // sum_s w (normalized, atomic)
__device__ float g_up[16*Bq*Oq*Hq];        // split-s partials of u (normalized)
__device__ float g_u[Bq*Oq*Hq];            // sum_s w * x (normalized)
__device__ float g_opout[Bq*Oq*Hq];        // operator outputs

// ---------------- K-zero -----------------------------------------------------
__global__ void kzero() {
    int i = blockIdx.x * 256 + threadIdx.x;
    if (i < Oq*Hq) g_oq[i] = 0.f;
    if (i < Bq*Oq) { g_esum[i] = 0.f; g_W[i] = 0.f; }
}

// ---------------- K0a: oq[o][h] = sum_s ops[s][o] * Wq_op[h][s] --------------
__global__ void __launch_bounds__(512) k0a(const float* __restrict__ Wq_op,
                                           const float* __restrict__ ops) {
    __shared__ float ops_sh[128*16];
    __shared__ float wq_sh[64][129];
    int h0 = blockIdx.x * 64, s0 = blockIdx.y * 128;
    for (int i = threadIdx.x; i < 128*16; i += 512)
        ops_sh[i] = ops[s0*16 + i];
    for (int i = threadIdx.x; i < 64*128; i += 512) {
        int r = i >> 7, c = i & 127;
        wq_sh[r][c] = Wq_op[(size_t)(h0 + r)*Sq + s0 + c];
    }
    __syncthreads();
    int hl = threadIdx.x & 63;
    int og = threadIdx.x >> 6;
    float a0 = 0.f, a1 = 0.f;
    #pragma unroll 8
    for (int s = 0; s < 128; s++) {
        float wv = wq_sh[hl][s];
        a0 += wv * ops_sh[s*16 + og*2];
        a1 += wv * ops_sh[s*16 + og*2 + 1];
    }
    atomicAdd(&g_oq[(og*2    )*Hq + h0 + hl], a0);
    atomicAdd(&g_oq[(og*2 + 1)*Hq + h0 + hl], a1);
}

// ---------------- K0b: kq[o][k] = (oq+bq)@Wk * rs; c = bk.(oq+bq)*rs ---------
__global__ void __launch_bounds__(128) k0b(const float* __restrict__ Wk,
                                           const float* __restrict__ bk,
                                           const float* __restrict__ bq,
                                           float* oq_out) {
    __shared__ float oq_sh[Hq];
    __shared__ float red[4][33];
    __shared__ float cr[128];
    int o = blockIdx.x, kc = blockIdx.y;
    for (int h = threadIdx.x; h < Hq; h += 128) {
        float v = g_oq[o*Hq + h] + bq[h];
        oq_sh[h] = v;
        if (kc == 0 && oq_out) oq_out[o*Hq + h] = v;
    }
    __syncthreads();
    int kl = threadIdx.x & 31, hq = threadIdx.x >> 5;
    int k = kc*32 + kl;
    const float* wp = Wk + (size_t)(hq*128)*Hq + k;
    float a = 0.f;
    #pragma unroll 16
    for (int h = 0; h < 128; h++)
        a += oq_sh[hq*128 + h] * wp[(size_t)h*Hq];
    red[hq][kl] = a;
    __syncthreads();
    if (hq == 0)
        g_kq[o*Hq + k] = (red[0][kl] + red[1][kl] + red[2][kl] + red[3][kl]) * RSQRT_H;
    if (kc == 0) {
        float cl = 0.f;
        for (int h = threadIdx.x; h < Hq; h += 128) cl += bk[h] * oq_sh[h];
        cr[threadIdx.x] = cl;
        __syncthreads();
        for (int st = 64; st > 0; st >>= 1) {
            if (threadIdx.x < st) cr[threadIdx.x] += cr[threadIdx.x + st];
            __syncthreads();
        }
        if (threadIdx.x == 0) g_c[o] = cr[0] * RSQRT_H;
    }
}

// fold-reduce 8 ull (f32x2 pairs) over 32 lanes; after: lane l (even, <16)
// holds pair index p = (l>>1)&7 in v[0]
__device__ __forceinline__ void fold8(ull v[8], int lane) {
    #pragma unroll
    for (int i = 0; i < 8; i++)
        v[i] = addf2(v[i], __shfl_xor_sync(0xffffffffu, v[i], 16));
    #pragma unroll
    for (int i = 0; i < 4; i++) {
        ull mn = (lane & 8) ? v[i+4] : v[i];
        ull th = (lane & 8) ? v[i] : v[i+4];
        v[i] = addf2(mn, __shfl_xor_sync(0xffffffffu, th, 8));
    }
    #pragma unroll
    for (int i = 0; i < 2; i++) {
        ull mn = (lane & 4) ? v[i+2] : v[i];
        ull th = (lane & 4) ? v[i] : v[i+2];
        v[i] = addf2(mn, __shfl_xor_sync(0xffffffffu, th, 4));
    }
    {
        ull mn = (lane & 2) ? v[1] : v[0];
        ull th = (lane & 2) ? v[0] : v[1];
        v[0] = addf2(mn, __shfl_xor_sync(0xffffffffu, th, 2));
    }
    v[0] = addf2(v[0], __shfl_xor_sync(0xffffffffu, v[0], 1));
}

// ---------------- K1: logits = x.kq + c; fused esum --------------------------
// o-split FFMA2: 8 warps = 4 row-groups x 2 o-halves; 16 rows/block, grid 2048
__global__ void __launch_bounds__(256) k1(const float* __restrict__ x) {
    __shared__ __align__(16) float kq_sh[Oq*Hq];   // 32KB [o][k]
    __shared__ float c_sh[16];
    __shared__ float st[16*16];
    __shared__ float esr[16][17];
    int tid = threadIdx.x;
    for (int i = tid; i < Oq*Hq/4; i += 256)
        ((float4*)kq_sh)[i] = ((const float4*)g_kq)[i];
    if (tid < 16) c_sh[tid] = g_c[tid];
    __syncthreads();

    int wid = tid >> 5, lane = tid & 31;
    int rg = wid >> 1, oh = wid & 1;
    size_t row0 = (size_t)blockIdx.x * 16;

    {
        const ulonglong2* xr = ((const ulonglong2*)x) + (row0 + rg*4) * 128;
        const ulonglong2* kq2 = (const ulonglong2*)kq_sh;
        ull acc[4][8];
        #pragma unroll
        for (int r = 0; r < 4; r++)
            #pragma unroll
            for (int o = 0; o < 8; o++) acc[r][o] = 0ull;
        #pragma unroll
        for (int jj = 0; jj < 4; jj++) {
            int j = jj*32 + lane;
            ulonglong2 x0 = xr[j], x1 = xr[128+j], x2 = xr[256+j], x3 = xr[384+j];
            #pragma unroll
            for (int o = 0; o < 8; o++) {
                ulonglong2 kv = kq2[(oh*8 + o)*128 + j];
                acc[0][o] = ffma2(x0.x, kv.x, acc[0][o]);
                acc[0][o] = ffma2(x0.y, kv.y, acc[0][o]);
                acc[1][o] = ffma2(x1.x, kv.x, acc[1][o]);
                acc[1][o] = ffma2(x1.y, kv.y, acc[1][o]);
                acc[2][o] = ffma2(x2.x, kv.x, acc[2][o]);
                acc[2][o] = ffma2(x2.y, kv.y, acc[2][o]);
                acc[3][o] = ffma2(x3.x, kv.x, acc[3][o]);
                acc[3][o] = ffma2(x3.y, kv.y, acc[3][o]);
            }
        }
        #pragma unroll
        for (int r = 0; r < 4; r++) {
            fold8(acc[r], lane);
            if (lane < 16 && !(lane & 1)) {
                float lo, hi;
                asm("mov.b64 {%0,%1}, %2;" : "=f"(lo), "=f"(hi) : "l"(acc[r][0]));
                st[(rg*4 + r)*16 + oh*8 + ((lane >> 1) & 7)] = lo + hi;
            }
        }
    }
    __syncthreads();
    // epilogue: +c, store logits (coalesced), exp-sum
    float v = st[tid] + c_sh[tid & 15];
    g_logits[row0*16 + tid] = v;
    float e = __expf(v);
    esr[tid >> 4][tid & 15] = e;
    __syncthreads();
    if (tid < 16) {
        float s = 0.f;
        #pragma unroll
        for (int j = 0; j < 16; j++) s += esr[j][tid];
        int b = blockIdx.x >> 7;    // 16 rows/block, 128 blocks per batch
        atomicAdd(&g_esum[b*16 + tid], s);
    }
}

// ---------------- K2: split-s partials of u = sum_s w*x (w normalized) ------
// grid (16 sc, 16 b), 256 threads; thread owns k=tid, tid+256; 128 s per block
__global__ void __launch_bounds__(256) k2(const float* __restrict__ x,
                                          const float* __restrict__ ops) {
    __shared__ __align__(16) float w_sh[128*16];   // 8KB
    __shared__ float inv_sh[16];
    __shared__ float wr[16][17];
    int sc = blockIdx.x, b = blockIdx.y;
    int tid = threadIdx.x;
    int s0 = sc * 128;
    if (tid < 16) inv_sh[tid] = 1.0f / g_esum[b*16 + tid];
    __syncthreads();
    const float* L  = g_logits + ((size_t)b*Sq + s0)*16;
    const float* op = ops + (size_t)s0*16;
    float Wloc = 0.f;
    #pragma unroll
    for (int t = 0; t < 8; t++) {
        int i = t*256 + tid;
        float wv = __expf(L[i]) * inv_sh[i & 15] * op[i];
        w_sh[i] = wv;
        Wloc += wv;
    }
    wr[tid >> 4][tid & 15] = Wloc;
    __syncthreads();
    if (tid < 16) {
        float s = 0.f;
        #pragma unroll
        for (int j = 0; j < 16; j++) s += wr[j][tid];
        atomicAdd(&g_W[b*16 + tid], s);
    }
    const float* xq = x + ((size_t)b*Sq + s0)*Hq + tid;
    ull a0[8], a1[8];
    #pragma unroll
    for (int j = 0; j < 8; j++) { a0[j] = 0ull; a1[j] = 0ull; }
    #pragma unroll 8
    for (int s = 0; s < 128; s++) {
        float xv0 = xq[(size_t)s*Hq];
        float xv1 = xq[(size_t)s*Hq + 256];
        ull xa = dup2(xv0), xb = dup2(xv1);
        const ull* w8 = (const ull*)(w_sh + s*16);
        #pragma unroll
        for (int j = 0; j < 8; j++) {
            ull wv = w8[j];
            a0[j] = ffma2(xa, wv, a0[j]);
            a1[j] = ffma2(xb, wv, a1[j]);
        }
    }
    float* up = g_up + (size_t)(sc*16 + b)*16*512;
    #pragma unroll
    for (int j = 0; j < 8; j++) {
        float lo, hi;
        asm("mov.b64 {%0,%1}, %2;" : "=f"(lo), "=f"(hi) : "l"(a0[j]));
        up[(2*j)*512 + tid]         = lo;
        up[(2*j+1)*512 + tid]       = hi;
        asm("mov.b64 {%0,%1}, %2;" : "=f"(lo), "=f"(hi) : "l"(a1[j]));
        up[(2*j)*512 + tid + 256]   = lo;
        up[(2*j+1)*512 + tid + 256] = hi;
    }
}

// ---------------- Ksum: u = sum of 16 split-s partials -----------------------
__global__ void ksum() {
    int i = blockIdx.x*256 + threadIdx.x;   // 32768 float4s
    int b = i >> 11, w4 = i & 2047;
    const float4* up4 = (const float4*)g_up;
    float4 s = up4[(size_t)b*2048 + w4];
    #pragma unroll
    for (int p = 1; p < 16; p++) {
        float4 t = up4[(size_t)(p*16 + b)*2048 + w4];
        s.x += t.x; s.y += t.y; s.z += t.z; s.w += t.w;
    }
    ((float4*)g_u)[i] = s;
}

// fold-reduce 16 floats over 32 lanes; lane l (<16) ends holding total of v[l]
__device__ __forceinline__ float fold16(float v[16], int lane) {
    #pragma unroll
    for (int i = 0; i < 16; i++)
        v[i] += __shfl_xor_sync(0xffffffffu, v[i], 16);
    #pragma unroll
    for (int i = 0; i < 8; i++) {
        float mn = (lane & 8) ? v[i+8] : v[i];
        float th = (lane & 8) ? v[i] : v[i+8];
        v[i] = mn + __shfl_xor_sync(0xffffffffu, th, 8);
    }
    #pragma unroll
    for (int i = 0; i < 4; i++) {
        float mn = (lane & 4) ? v[i+4] : v[i];
        float th = (lane & 4) ? v[i] : v[i+4];
        v[i] = mn + __shfl_xor_sync(0xffffffffu, th, 4);
    }
    #pragma unroll
    for (int i = 0; i < 2; i++) {
        float mn = (lane & 2) ? v[i+2] : v[i];
        float th = (lane & 2) ? v[i] : v[i+2];
        v[i] = mn + __shfl_xor_sync(0xffffffffu, th, 2);
    }
    {
        float mn = (lane & 1) ? v[1] : v[0];
        float th = (lane & 1) ? v[0] : v[1];
        v[0] = mn + __shfl_xor_sync(0xffffffffu, th, 1);
    }
    return v[0];
}

// ---------------- K3: op_out[b,o,h] = u[b,o,:].Wv[h,:] + bv[h]*W[b,o] -------
// grid (16 o, 8 hc of 64), 256 threads (8 warps)
__global__ void __launch_bounds__(256) k3(const float* __restrict__ Wv,
                                          const float* __restrict__ bv) {
    __shared__ float4 u4[16*128];
    __shared__ float Wsh[16];
    int o = blockIdx.x, hc = blockIdx.y;
    for (int i = threadIdx.x; i < 16*128; i += 256) {
        int b = i >> 7, k4 = i & 127;
        u4[i] = ((const float4*)g_u)[((size_t)b*16 + o)*128 + k4];
    }
    if (threadIdx.x < 16) Wsh[threadIdx.x] = g_W[threadIdx.x*16 + o];
    __syncthreads();
    int wid = threadIdx.x >> 5, lane = threadIdx.x & 31;
    for (int q = 0; q < 2; q++) {
        int h = hc*64 + wid*8 + q*4;
        const float4* wv = ((const float4*)Wv) + (size_t)h * 128;
        float acc[4][16];
        #pragma unroll
        for (int r = 0; r < 4; r++)
            #pragma unroll
            for (int b = 0; b < 16; b++) acc[r][b] = 0.f;
        #pragma unroll
        for (int jj = 0; jj < 4; jj++) {
            int j = jj*32 + lane;
            float4 v0 = wv[j], v1 = wv[128+j], v2 = wv[256+j], v3 = wv[384+j];
            #pragma unroll
            for (int b = 0; b < 16; b++) {
                float4 uu = u4[b*128 + j];
                acc[0][b] += v0.x*uu.x + v0.y*uu.y + v0.z*uu.z + v0.w*uu.w;
                acc[1][b] += v1.x*uu.x + v1.y*uu.y + v1.z*uu.z + v1.w*uu.w;
                acc[2][b] += v2.x*uu.x + v2.y*uu.y + v2.z*uu.z + v2.w*uu.w;
                acc[3][b] += v3.x*uu.x + v3.y*uu.y + v3.z*uu.z + v3.w*uu.w;
            }
        }
        #pragma unroll
        for (int r = 0; r < 4; r++) {
            float t = fold16(acc[r], lane);
            if (lane < 16)
                g_opout[((size_t)lane*16 + o)*Hq + h + r] = t + bv[h + r] * Wsh[lane];
        }
    }
}

// ---------------- K4: out[b,s,h] = sum_o softmax_o(L)[o]*op_out[b,o,h] ------
__global__ void __launch_bounds__(256) k4(float* __restrict__ out) {
    __shared__ __align__(16) float4 op4[16*128];
    int b = blockIdx.y, sc = blockIdx.x;
    for (int i = threadIdx.x; i < 16*128; i += 256)
        op4[i] = ((const float4*)g_opout)[(size_t)b*2048 + i];
    __syncthreads();
    int wid = threadIdx.x >> 5, lane = threadIdx.x & 31;
    for (int q = 0; q < 2; q++) {
        int s0 = sc*64 + wid*8 + q*4;
        size_t r0 = (size_t)b*Sq + s0;
        const float* lp = g_logits + (r0 + (lane & 3)) * 16;
        float e[16];
        float mx = -1e30f;
        #pragma unroll
        for (int o = 0; o < 16; o++) { e[o] = lp[o]; mx = fmaxf(mx, e[o]); }
        float sum = 0.f;
        #pragma unroll
        for (int o = 0; o < 16; o++) { e[o] = __expf(e[o] - mx); sum += e[o]; }
        float inv = 1.0f / sum;
        float ow0[16], ow1[16], ow2[16], ow3[16];
        #pragma unroll
        for (int o = 0; o < 16; o++) {
            float v = e[o] * inv;
            ow0[o] = __shfl_sync(0xffffffffu, v, 0, 4);
            ow1[o] = __shfl_sync(0xffffffffu, v, 1, 4);
            ow2[o] = __shfl_sync(0xffffffffu, v, 2, 4);
            ow3[o] = __shfl_sync(0xffffffffu, v, 3, 4);
        }
        ulonglong2* o2 = (ulonglong2*)(((float4*)out) + r0 * 128);
        #pragma unroll
        for (int jj = 0; jj < 4; jj++) {
            int j = jj*32 + lane;
            ull A0[2] = {0ull,0ull}, A1[2] = {0ull,0ull};
            ull A2[2] = {0ull,0ull}, A3[2] = {0ull,0ull};
            #pragma unroll
            for (int o = 0; o < 16; o++) {
                ulonglong2 kk = ((const ulonglong2*)op4)[o*128 + j];
                ull d0 = dup2(ow0[o]), d1 = dup2(ow1[o]);
                ull d2 = dup2(ow2[o]), d3 = dup2(ow3[o]);
                A0[0] = ffma2(d0, kk.x, A0[0]); A0[1] = ffma2(d0, kk.y, A0[1]);
                A1[0] = ffma2(d1, kk.x, A1[0]); A1[1] = ffma2(d1, kk.y, A1[1]);
                A2[0] = ffma2(d2, kk.x, A2[0]); A2[1] = ffma2(d2, kk.y, A2[1]);
                A3[0] = ffma2(d3, kk.x, A3[0]); A3[1] = ffma2(d3, kk.y, A3[1]);
            }
            o2[j]        = make_ulonglong2(A0[0], A0[1]);
            o2[128 + j]  = make_ulonglong2(A1[0], A1[1]);
            o2[256 + j]  = make_ulonglong2(A2[0], A2[1]);
            o2[384 + j]  = make_ulonglong2(A3[0], A3[1]);
        }
    }
}

// ---------------------------------------------------------------------------
extern "C" void kernel_launch(void* const* d_in, const int* in_sizes, int n_in,
                              void* d_out, int out_size) {
    const float* x     = (const float*)d_in[0];
    const float* Wv    = (const float*)d_in[1];
    const float* bv    = (const float*)d_in[2];
    const float* Wk    = (const float*)d_in[3];
    const float* bk    = (const float*)d_in[4];
    const float* Wq_op = (const float*)d_in[5];
    const float* bq_op = (const float*)d_in[6];
    const float* ops   = (const float*)d_in[7];
    (void)in_sizes; (void)n_in;
    float* out = (float*)d_out;
    float* oq_out = (out_size >= Bq*Sq*Hq + Oq*Hq) ? out + (size_t)Bq*Sq*Hq : nullptr;

    kzero<<<32, 256>>>();
    k0a<<<dim3(8, 16), 512>>>(Wq_op, ops);
    k0b<<<dim3(16, 16), 128>>>(Wk, bk, bq_op, oq_out);
    k1<<<BSq/16, 256>>>(x);
    k2<<<dim3(16, 16), 256>>>(x, ops);
    ksum<<<128, 256>>>();
    k3<<<dim3(16, 8), 256>>>(Wv, bv);
    k4<<<dim3(32, 16), 256>>>(out);
}

// round 7
// speedup vs baseline: 1.1170x; 1.0868x over previous
#include <cuda_runtime.h>
#include <math.h>

#define Bq 16
#define Sq 2048
#define Hq 512
#define Oq 16
#define BSq (Bq*Sq)            // 32768
#define RSQRT_H 0.04419417382415922f   // 1/sqrt(512)

typedef unsigned long long ull;

__device__ __forceinline__ ull ffma2(ull a, ull b, ull c) {
    ull d; asm("fma.rn.f32x2 %0, %1, %2, %3;" : "=l"(d) : "l"(a), "l"(b), "l"(c));
    return d;
}
__device__ __forceinline__ ull addf2(ull a, ull b) {
    ull d; asm("add.rn.f32x2 %0, %1, %2;" : "=l"(d) : "l"(a), "l"(b));
    return d;
}
__device__ __forceinline__ ull dup2(float f) {
    ull r; asm("mov.b64 %0, {%1, %1};" : "=l"(r) : "f"(f));
    return r;
}

// ---------------- scratch (device globals) ----------------------------------
__device__ float g_oq[Oq*Hq];              // raw operator queries (atomic accum)
__device__ float g_kq[Oq*Hq];              // oq @ Wk, pre-scaled  [o][k]
__device__ float g_c[Oq];                  // bk . oq, pre-scaled
__device__ float g_logits[BSq*Oq];         // [b][s][o]
__device__ float g_esum[Bq*Oq];            // sum_s exp(logits)  (atomic)
__device__ float g_W[Bq*Oq];               // sum_s w (normalized, atomic)
__device__ float g_up[16*Bq*Oq*Hq];        // split-s partials of u (normalized)
__device__ float g_u[Bq*Oq*Hq];            // sum_s w * x (normalized)
__device__ float g_opout[Bq*Oq*Hq];        // operator outputs

// ---------------- K-zero -----------------------------------------------------
__global__ void kzero() {
    int i = blockIdx.x * 256 + threadIdx.x;
    if (i < Oq*Hq) g_oq[i] = 0.f;
    if (i < Bq*Oq) { g_esum[i] = 0.f; g_W[i] = 0.f; }
}

// ---------------- K0a: oq[o][h] = sum_s ops[s][o] * Wq_op[h][s] --------------
__global__ void __launch_bounds__(512) k0a(const float* __restrict__ Wq_op,
                                           const float* __restrict__ ops) {
    __shared__ float ops_sh[128*16];
    __shared__ float wq_sh[64][129];
    int h0 = blockIdx.x * 64, s0 = blockIdx.y * 128;
    for (int i = threadIdx.x; i < 128*16; i += 512)
        ops_sh[i] = ops[s0*16 + i];
    for (int i = threadIdx.x; i < 64*128; i += 512) {
        int r = i >> 7, c = i & 127;
        wq_sh[r][c] = Wq_op[(size_t)(h0 + r)*Sq + s0 + c];
    }
    __syncthreads();
    int hl = threadIdx.x & 63;
    int og = threadIdx.x >> 6;
    float a0 = 0.f, a1 = 0.f;
    #pragma unroll 8
    for (int s = 0; s < 128; s++) {
        float wv = wq_sh[hl][s];
        a0 += wv * ops_sh[s*16 + og*2];
        a1 += wv * ops_sh[s*16 + og*2 + 1];
    }
    atomicAdd(&g_oq[(og*2    )*Hq + h0 + hl], a0);
    atomicAdd(&g_oq[(og*2 + 1)*Hq + h0 + hl], a1);
}

// ---------------- K0b: kq[o][k] = (oq+bq)@Wk * rs; c = bk.(oq+bq)*rs ---------
__global__ void __launch_bounds__(128) k0b(const float* __restrict__ Wk,
                                           const float* __restrict__ bk,
                                           const float* __restrict__ bq,
                                           float* oq_out) {
    __shared__ float oq_sh[Hq];
    __shared__ float red[4][33];
    __shared__ float cr[128];
    int o = blockIdx.x, kc = blockIdx.y;
    for (int h = threadIdx.x; h < Hq; h += 128) {
        float v = g_oq[o*Hq + h] + bq[h];
        oq_sh[h] = v;
        if (kc == 0 && oq_out) oq_out[o*Hq + h] = v;
    }
    __syncthreads();
    int kl = threadIdx.x & 31, hq = threadIdx.x >> 5;
    int k = kc*32 + kl;
    const float* wp = Wk + (size_t)(hq*128)*Hq + k;
    float a = 0.f;
    #pragma unroll 16
    for (int h = 0; h < 128; h++)
        a += oq_sh[hq*128 + h] * wp[(size_t)h*Hq];
    red[hq][kl] = a;
    __syncthreads();
    if (hq == 0)
        g_kq[o*Hq + k] = (red[0][kl] + red[1][kl] + red[2][kl] + red[3][kl]) * RSQRT_H;
    if (kc == 0) {
        float cl = 0.f;
        for (int h = threadIdx.x; h < Hq; h += 128) cl += bk[h] * oq_sh[h];
        cr[threadIdx.x] = cl;
        __syncthreads();
        for (int st = 64; st > 0; st >>= 1) {
            if (threadIdx.x < st) cr[threadIdx.x] += cr[threadIdx.x + st];
            __syncthreads();
        }
        if (threadIdx.x == 0) g_c[o] = cr[0] * RSQRT_H;
    }
}

// fold-reduce 8 ull (f32x2 pairs) over 32 lanes; after: lane l (even, <16)
// holds pair index p = (l>>1)&7 in v[0]
__device__ __forceinline__ void fold8(ull v[8], int lane) {
    #pragma unroll
    for (int i = 0; i < 8; i++)
        v[i] = addf2(v[i], __shfl_xor_sync(0xffffffffu, v[i], 16));
    #pragma unroll
    for (int i = 0; i < 4; i++) {
        ull mn = (lane & 8) ? v[i+4] : v[i];
        ull th = (lane & 8) ? v[i] : v[i+4];
        v[i] = addf2(mn, __shfl_xor_sync(0xffffffffu, th, 8));
    }
    #pragma unroll
    for (int i = 0; i < 2; i++) {
        ull mn = (lane & 4) ? v[i+2] : v[i];
        ull th = (lane & 4) ? v[i] : v[i+2];
        v[i] = addf2(mn, __shfl_xor_sync(0xffffffffu, th, 4));
    }
    {
        ull mn = (lane & 2) ? v[1] : v[0];
        ull th = (lane & 2) ? v[0] : v[1];
        v[0] = addf2(mn, __shfl_xor_sync(0xffffffffu, th, 2));
    }
    v[0] = addf2(v[0], __shfl_xor_sync(0xffffffffu, v[0], 1));
}

// ---------------- K1: logits = x.kq + c; fused esum --------------------------
// o-split FFMA2: 8 warps = 4 row-groups x 2 o-halves; 16 rows/block, grid 2048
// __launch_bounds__(256, 2): cap regs at 128 so 2 CTAs/SM fit (R6 had 132 -> 1 CTA)
__global__ void __launch_bounds__(256, 2) k1(const float* __restrict__ x) {
    __shared__ __align__(16) float kq_sh[Oq*Hq];   // 32KB [o][k]
    __shared__ float c_sh[16];
    __shared__ float st[16*16];
    __shared__ float esr[16][17];
    int tid = threadIdx.x;
    for (int i = tid; i < Oq*Hq/4; i += 256)
        ((float4*)kq_sh)[i] = ((const float4*)g_kq)[i];
    if (tid < 16) c_sh[tid] = g_c[tid];
    __syncthreads();

    int wid = tid >> 5, lane = tid & 31;
    int rg = wid >> 1, oh = wid & 1;
    size_t row0 = (size_t)blockIdx.x * 16;

    {
        const ulonglong2* xr = ((const ulonglong2*)x) + (row0 + rg*4) * 128;
        const ulonglong2* kq2 = (const ulonglong2*)kq_sh;
        ull acc[4][8];
        #pragma unroll
        for (int r = 0; r < 4; r++)
            #pragma unroll
            for (int o = 0; o < 8; o++) acc[r][o] = 0ull;
        #pragma unroll
        for (int jj = 0; jj < 4; jj++) {
            int j = jj*32 + lane;
            ulonglong2 x0 = xr[j], x1 = xr[128+j], x2 = xr[256+j], x3 = xr[384+j];
            #pragma unroll
            for (int o = 0; o < 8; o++) {
                ulonglong2 kv = kq2[(oh*8 + o)*128 + j];
                acc[0][o] = ffma2(x0.x, kv.x, acc[0][o]);
                acc[0][o] = ffma2(x0.y, kv.y, acc[0][o]);
                acc[1][o] = ffma2(x1.x, kv.x, acc[1][o]);
                acc[1][o] = ffma2(x1.y, kv.y, acc[1][o]);
                acc[2][o] = ffma2(x2.x, kv.x, acc[2][o]);
                acc[2][o] = ffma2(x2.y, kv.y, acc[2][o]);
                acc[3][o] = ffma2(x3.x, kv.x, acc[3][o]);
                acc[3][o] = ffma2(x3.y, kv.y, acc[3][o]);
            }
        }
        #pragma unroll
        for (int r = 0; r < 4; r++) {
            fold8(acc[r], lane);
            if (lane < 16 && !(lane & 1)) {
                float lo, hi;
                asm("mov.b64 {%0,%1}, %2;" : "=f"(lo), "=f"(hi) : "l"(acc[r][0]));
                st[(rg*4 + r)*16 + oh*8 + ((lane >> 1) & 7)] = lo + hi;
            }
        }
    }
    __syncthreads();
    // epilogue: +c, store logits (coalesced), exp-sum
    float v = st[tid] + c_sh[tid & 15];
    g_logits[row0*16 + tid] = v;
    float e = __expf(v);
    esr[tid >> 4][tid & 15] = e;
    __syncthreads();
    if (tid < 16) {
        float s = 0.f;
        #pragma unroll
        for (int j = 0; j < 16; j++) s += esr[j][tid];
        int b = blockIdx.x >> 7;    // 16 rows/block, 128 blocks per batch
        atomicAdd(&g_esum[b*16 + tid], s);
    }
}

// ---------------- K2: split-s partials of u = sum_s w*x (w normalized) ------
// grid (16 sc, 16 b), 256 threads; thread owns k=tid, tid+256; 128 s per block
__global__ void __launch_bounds__(256) k2(const float* __restrict__ x,
                                          const float* __restrict__ ops) {
    __shared__ __align__(16) float w_sh[128*16];   // 8KB
    __shared__ float inv_sh[16];
    __shared__ float wr[16][17];
    int sc = blockIdx.x, b = blockIdx.y;
    int tid = threadIdx.x;
    int s0 = sc * 128;
    if (tid < 16) inv_sh[tid] = 1.0f / g_esum[b*16 + tid];
    __syncthreads();
    const float* L  = g_logits + ((size_t)b*Sq + s0)*16;
    const float* op = ops + (size_t)s0*16;
    float Wloc = 0.f;
    #pragma unroll
    for (int t = 0; t < 8; t++) {
        int i = t*256 + tid;
        float wv = __expf(L[i]) * inv_sh[i & 15] * op[i];
        w_sh[i] = wv;
        Wloc += wv;
    }
    wr[tid >> 4][tid & 15] = Wloc;
    __syncthreads();
    if (tid < 16) {
        float s = 0.f;
        #pragma unroll
        for (int j = 0; j < 16; j++) s += wr[j][tid];
        atomicAdd(&g_W[b*16 + tid], s);
    }
    const float* xq = x + ((size_t)b*Sq + s0)*Hq + tid;
    ull a0[8], a1[8];
    #pragma unroll
    for (int j = 0; j < 8; j++) { a0[j] = 0ull; a1[j] = 0ull; }
    #pragma unroll 8
    for (int s = 0; s < 128; s++) {
        float xv0 = xq[(size_t)s*Hq];
        float xv1 = xq[(size_t)s*Hq + 256];
        ull xa = dup2(xv0), xb = dup2(xv1);
        const ull* w8 = (const ull*)(w_sh + s*16);
        #pragma unroll
        for (int j = 0; j < 8; j++) {
            ull wv = w8[j];
            a0[j] = ffma2(xa, wv, a0[j]);
            a1[j] = ffma2(xb, wv, a1[j]);
        }
    }
    float* up = g_up + (size_t)(sc*16 + b)*16*512;
    #pragma unroll
    for (int j = 0; j < 8; j++) {
        float lo, hi;
        asm("mov.b64 {%0,%1}, %2;" : "=f"(lo), "=f"(hi) : "l"(a0[j]));
        up[(2*j)*512 + tid]         = lo;
        up[(2*j+1)*512 + tid]       = hi;
        asm("mov.b64 {%0,%1}, %2;" : "=f"(lo), "=f"(hi) : "l"(a1[j]));
        up[(2*j)*512 + tid + 256]   = lo;
        up[(2*j+1)*512 + tid + 256] = hi;
    }
}

// ---------------- Ksum: u = sum of 16 split-s partials -----------------------
__global__ void ksum() {
    int i = blockIdx.x*256 + threadIdx.x;   // 32768 float4s
    int b = i >> 11, w4 = i & 2047;
    const float4* up4 = (const float4*)g_up;
    float4 s = up4[(size_t)b*2048 + w4];
    #pragma unroll
    for (int p = 1; p < 16; p++) {
        float4 t = up4[(size_t)(p*16 + b)*2048 + w4];
        s.x += t.x; s.y += t.y; s.z += t.z; s.w += t.w;
    }
    ((float4*)g_u)[i] = s;
}

// fold-reduce 16 floats over 32 lanes; lane l (<16) ends holding total of v[l]
__device__ __forceinline__ float fold16(float v[16], int lane) {
    #pragma unroll
    for (int i = 0; i < 16; i++)
        v[i] += __shfl_xor_sync(0xffffffffu, v[i], 16);
    #pragma unroll
    for (int i = 0; i < 8; i++) {
        float mn = (lane & 8) ? v[i+8] : v[i];
        float th = (lane & 8) ? v[i] : v[i+8];
        v[i] = mn + __shfl_xor_sync(0xffffffffu, th, 8);
    }
    #pragma unroll
    for (int i = 0; i < 4; i++) {
        float mn = (lane & 4) ? v[i+4] : v[i];
        float th = (lane & 4) ? v[i] : v[i+4];
        v[i] = mn + __shfl_xor_sync(0xffffffffu, th, 4);
    }
    #pragma unroll
    for (int i = 0; i < 2; i++) {
        float mn = (lane & 2) ? v[i+2] : v[i];
        float th = (lane & 2) ? v[i] : v[i+2];
        v[i] = mn + __shfl_xor_sync(0xffffffffu, th, 2);
    }
    {
        float mn = (lane & 1) ? v[1] : v[0];
        float th = (lane & 1) ? v[0] : v[1];
        v[0] = mn + __shfl_xor_sync(0xffffffffu, th, 1);
    }
    return v[0];
}

// ---------------- K3: op_out[b,o,h] = u[b,o,:].Wv[h,:] + bv[h]*W[b,o] -------
// grid (16 o, 8 hc of 64), 256 threads (8 warps)
__global__ void __launch_bounds__(256) k3(const float* __restrict__ Wv,
                                          const float* __restrict__ bv) {
    __shared__ float4 u4[16*128];
    __shared__ float Wsh[16];
    int o = blockIdx.x, hc = blockIdx.y;
    for (int i = threadIdx.x; i < 16*128; i += 256) {
        int b = i >> 7, k4 = i & 127;
        u4[i] = ((const float4*)g_u)[((size_t)b*16 + o)*128 + k4];
    }
    if (threadIdx.x < 16) Wsh[threadIdx.x] = g_W[threadIdx.x*16 + o];
    __syncthreads();
    int wid = threadIdx.x >> 5, lane = threadIdx.x & 31;
    for (int q = 0; q < 2; q++) {
        int h = hc*64 + wid*8 + q*4;
        const float4* wv = ((const float4*)Wv) + (size_t)h * 128;
        float acc[4][16];
        #pragma unroll
        for (int r = 0; r < 4; r++)
            #pragma unroll
            for (int b = 0; b < 16; b++) acc[r][b] = 0.f;
        #pragma unroll
        for (int jj = 0; jj < 4; jj++) {
            int j = jj*32 + lane;
            float4 v0 = wv[j], v1 = wv[128+j], v2 = wv[256+j], v3 = wv[384+j];
            #pragma unroll
            for (int b = 0; b < 16; b++) {
                float4 uu = u4[b*128 + j];
                acc[0][b] += v0.x*uu.x + v0.y*uu.y + v0.z*uu.z + v0.w*uu.w;
                acc[1][b] += v1.x*uu.x + v1.y*uu.y + v1.z*uu.z + v1.w*uu.w;
                acc[2][b] += v2.x*uu.x + v2.y*uu.y + v2.z*uu.z + v2.w*uu.w;
                acc[3][b] += v3.x*uu.x + v3.y*uu.y + v3.z*uu.z + v3.w*uu.w;
            }
        }
        #pragma unroll
        for (int r = 0; r < 4; r++) {
            float t = fold16(acc[r], lane);
            if (lane < 16)
                g_opout[((size_t)lane*16 + o)*Hq + h + r] = t + bv[h + r] * Wsh[lane];
        }
    }
}

// ---------------- K4: out[b,s,h] = sum_o softmax_o(L)[o]*op_out[b,o,h] ------
__global__ void __launch_bounds__(256) k4(float* __restrict__ out) {
    __shared__ __align__(16) float4 op4[16*128];
    int b = blockIdx.y, sc = blockIdx.x;
    for (int i = threadIdx.x; i < 16*128; i += 256)
        op4[i] = ((const float4*)g_opout)[(size_t)b*2048 + i];
    __syncthreads();
    int wid = threadIdx.x >> 5, lane = threadIdx.x & 31;
    for (int q = 0; q < 2; q++) {
        int s0 = sc*64 + wid*8 + q*4;
        size_t r0 = (size_t)b*Sq + s0;
        const float* lp = g_logits + (r0 + (lane & 3)) * 16;
        float e[16];
        float mx = -1e30f;
        #pragma unroll
        for (int o = 0; o < 16; o++) { e[o] = lp[o]; mx = fmaxf(mx, e[o]); }
        float sum = 0.f;
        #pragma unroll
        for (int o = 0; o < 16; o++) { e[o] = __expf(e[o] - mx); sum += e[o]; }
        float inv = 1.0f / sum;
        float ow0[16], ow1[16], ow2[16], ow3[16];
        #pragma unroll
        for (int o = 0; o < 16; o++) {
            float v = e[o] * inv;
            ow0[o] = __shfl_sync(0xffffffffu, v, 0, 4);
            ow1[o] = __shfl_sync(0xffffffffu, v, 1, 4);
            ow2[o] = __shfl_sync(0xffffffffu, v, 2, 4);
            ow3[o] = __shfl_sync(0xffffffffu, v, 3, 4);
        }
        ulonglong2* o2 = (ulonglong2*)(((float4*)out) + r0 * 128);
        #pragma unroll
        for (int jj = 0; jj < 4; jj++) {
            int j = jj*32 + lane;
            ull A0[2] = {0ull,0ull}, A1[2] = {0ull,0ull};
            ull A2[2] = {0ull,0ull}, A3[2] = {0ull,0ull};
            #pragma unroll
            for (int o = 0; o < 16; o++) {
                ulonglong2 kk = ((const ulonglong2*)op4)[o*128 + j];
                ull d0 = dup2(ow0[o]), d1 = dup2(ow1[o]);
                ull d2 = dup2(ow2[o]), d3 = dup2(ow3[o]);
                A0[0] = ffma2(d0, kk.x, A0[0]); A0[1] = ffma2(d0, kk.y, A0[1]);
                A1[0] = ffma2(d1, kk.x, A1[0]); A1[1] = ffma2(d1, kk.y, A1[1]);
                A2[0] = ffma2(d2, kk.x, A2[0]); A2[1] = ffma2(d2, kk.y, A2[1]);
                A3[0] = ffma2(d3, kk.x, A3[0]); A3[1] = ffma2(d3, kk.y, A3[1]);
            }
            o2[j]        = make_ulonglong2(A0[0], A0[1]);
            o2[128 + j]  = make_ulonglong2(A1[0], A1[1]);
            o2[256 + j]  = make_ulonglong2(A2[0], A2[1]);
            o2[384 + j]  = make_ulonglong2(A3[0], A3[1]);
        }
    }
}

// ---------------------------------------------------------------------------
extern "C" void kernel_launch(void* const* d_in, const int* in_sizes, int n_in,
                              void* d_out, int out_size) {
    const float* x     = (const float*)d_in[0];
    const float* Wv    = (const float*)d_in[1];
    const float* bv    = (const float*)d_in[2];
    const float* Wk    = (const float*)d_in[3];
    const float* bk    = (const float*)d_in[4];
    const float* Wq_op = (const float*)d_in[5];
    const float* bq_op = (const float*)d_in[6];
    const float* ops   = (const float*)d_in[7];
    (void)in_sizes; (void)n_in;
    float* out = (float*)d_out;
    float* oq_out = (out_size >= Bq*Sq*Hq + Oq*Hq) ? out + (size_t)Bq*Sq*Hq : nullptr;

    kzero<<<32, 256>>>();
    k0a<<<dim3(8, 16), 512>>>(Wq_op, ops);
    k0b<<<dim3(16, 16), 128>>>(Wk, bk, bq_op, oq_out);
    k1<<<BSq/16, 256>>>(x);
    k2<<<dim3(16, 16), 256>>>(x, ops);
    ksum<<<128, 256>>>();
    k3<<<dim3(16, 8), 256>>>(Wv, bv);
    k4<<<dim3(32, 16), 256>>>(out);
}